// round 11
// baseline (speedup 1.0000x reference)
#include <cuda_runtime.h>
#include <cuda_fp16.h>
#include <math.h>
#include <stdint.h>

#define NTOK 4096      // B*S
#define HDIM 1024
#define IDIM 3584
#define NEXP 8

// smem pitches in fp16 halves (all ldsm phases conflict-free)
#define AP  40    // A tile row: 32 k + 8 pad
#define BP  136   // B tile row: 128 n + 8
#define A_H  (64 * AP)    // 2560 halves / stage
#define B_H  (32 * BP)    // 4352 halves / stage

// ---------------- device scratch (no allocs) ----------------
__device__ int    g_cnt[NEXP];
__device__ int    g_tok[NEXP][NTOK];
__device__ float  g_wt [NEXP][NTOK];
__device__ __half g_act [(size_t)NEXP * NTOK * IDIM];   // fp16 activations

// ---------------- helpers ----------------
__device__ __forceinline__ uint32_t smem_u32(const void* p) {
    uint32_t a;
    asm("{ .reg .u64 t; cvta.to.shared.u64 t, %1; cvt.u32.u64 %0, t; }" : "=r"(a) : "l"(p));
    return a;
}
__device__ __forceinline__ void sts_h4(uint32_t addr, float4 v) {
    __half2 h0 = __floats2half2_rn(v.x, v.y);
    __half2 h1 = __floats2half2_rn(v.z, v.w);
    uint32_t u0 = *reinterpret_cast<uint32_t*>(&h0);
    uint32_t u1 = *reinterpret_cast<uint32_t*>(&h1);
    asm volatile("st.shared.v2.b32 [%0], {%1,%2};" :: "r"(addr), "r"(u0), "r"(u1) : "memory");
}
__device__ __forceinline__ void sts_u2(uint32_t addr, uint2 v) {
    asm volatile("st.shared.v2.b32 [%0], {%1,%2};" :: "r"(addr), "r"(v.x), "r"(v.y) : "memory");
}
__device__ __forceinline__ void ldsm4(uint32_t* r, uint32_t a) {
    asm volatile("ldmatrix.sync.aligned.m8n8.x4.shared.b16 {%0,%1,%2,%3}, [%4];"
                 : "=r"(r[0]), "=r"(r[1]), "=r"(r[2]), "=r"(r[3]) : "r"(a));
}
__device__ __forceinline__ void ldsm4t(uint32_t* r, uint32_t a) {
    asm volatile("ldmatrix.sync.aligned.m8n8.x4.trans.shared.b16 {%0,%1,%2,%3}, [%4];"
                 : "=r"(r[0]), "=r"(r[1]), "=r"(r[2]), "=r"(r[3]) : "r"(a));
}
__device__ __forceinline__ void mma16(float* d, const uint32_t* a, uint32_t b0, uint32_t b1) {
    asm volatile(
        "mma.sync.aligned.m16n8k16.row.col.f32.f16.f16.f32 "
        "{%0,%1,%2,%3},{%4,%5,%6,%7},{%8,%9},{%0,%1,%2,%3};"
        : "+f"(d[0]), "+f"(d[1]), "+f"(d[2]), "+f"(d[3])
        : "r"(a[0]), "r"(a[1]), "r"(a[2]), "r"(a[3]), "r"(b0), "r"(b1));
}

// ---------------------------------------------------------------------------
__global__ void zero_kernel(float4* __restrict__ out, int n4) {
    int i = blockIdx.x * blockDim.x + threadIdx.x;
    if (i < n4) out[i] = make_float4(0.f, 0.f, 0.f, 0.f);
    if (i < NEXP) g_cnt[i] = 0;
}

// ---------------------------------------------------------------------------
__global__ void router_kernel(const float* __restrict__ x,
                              const float* __restrict__ gw,
                              float* __restrict__ logits_out) {
    int t = blockIdx.x;
    __shared__ float xs[HDIM];
    __shared__ float lg[NEXP];
    int tid = threadIdx.x;
    for (int i = tid; i < HDIM; i += 256) xs[i] = x[(size_t)t * HDIM + i];
    __syncthreads();
    int w = tid >> 5, lane = tid & 31;
    float s = 0.f;
    for (int k = lane; k < HDIM; k += 32) s += xs[k] * gw[k * NEXP + w];
    #pragma unroll
    for (int o = 16; o; o >>= 1) s += __shfl_xor_sync(0xffffffffu, s, o);
    if (lane == 0) lg[w] = s;
    __syncthreads();
    if (tid == 0) {
        #pragma unroll
        for (int e = 0; e < NEXP; e++) logits_out[(size_t)t * NEXP + e] = lg[e];
        int b0 = 0; float v0 = lg[0];
        #pragma unroll
        for (int e = 1; e < NEXP; e++) if (lg[e] > v0) { v0 = lg[e]; b0 = e; }
        int b1 = -1; float v1 = -INFINITY;
        #pragma unroll
        for (int e = 0; e < NEXP; e++) if (e != b0 && lg[e] > v1) { v1 = lg[e]; b1 = e; }
        float p1  = expf(v1 - v0);
        float inv = 1.0f / (1.0f + p1);
        int p = atomicAdd(&g_cnt[b0], 1);
        g_tok[b0][p] = t; g_wt[b0][p] = inv;
        int q = atomicAdd(&g_cnt[b1], 1);
        g_tok[b1][q] = t; g_wt[b1][q] = p1 * inv;
    }
}

// ---------------------------------------------------------------------------
// FFN1: CTA 64(M)x128(N)xK32, 128 thr (4 warps 1Mx4N), warp 64x32 dual.
// 2 CTAs/SM (decoupled barriers). G = silu(X.w1)*(X.w3) -> fp16.
// ---------------------------------------------------------------------------
__global__ __launch_bounds__(128, 2)
void ffn1_mma(const float* __restrict__ x,
              const float* __restrict__ w1,
              const float* __restrict__ w3) {
    extern __shared__ __half smh[];
    __shared__ int toks[64];
    const int tid = threadIdx.x;
    const int e   = blockIdx.z;
    const int cnt = g_cnt[e];
    const int m0  = blockIdx.y * 64;
    if (m0 >= cnt) return;
    const int n0  = blockIdx.x * 128;

    if (tid < 64) {
        int r = m0 + tid;
        toks[tid] = (r < cnt) ? g_tok[e][r] : g_tok[e][0];
    }
    __syncthreads();
    const uint32_t sb = smem_u32(smh);
    const uint32_t oB1 = 2 * A_H * 2;                 // bytes
    const uint32_t oB3 = (2 * A_H + 2 * B_H) * 2;

    // staging: A 4 float4/thread (rows ra+16s), B1/B3 8 float4 each (k-rows kb+4s)
    const int fa = tid & 7,  ra = tid >> 3;    // ra 0..15
    const int fb = tid & 31, kb = tid >> 5;    // kb 0..3
    const float* ap[4];
    #pragma unroll
    for (int s = 0; s < 4; s++)
        ap[s] = x + (size_t)toks[ra + 16 * s] * HDIM + fa * 4;
    const float* W1 = w1 + (size_t)e * HDIM * IDIM + n0 + fb * 4;
    const float* W3 = w3 + (size_t)e * HDIM * IDIM + n0 + fb * 4;
    const uint32_t dA0 = (ra * AP + fa * 4) * 2;
    const uint32_t dB0 = (kb * BP + fb * 4) * 2;

    const int wid = tid >> 5, lane = tid & 31;
    const int wn = wid * 32;
    const int g = lane >> 2, t = lane & 3;
    const int rowoff = (lane & 8) + (lane & 7);
    const int khalf  = (lane & 16) >> 1;

    float acc1[4][4][4], acc3[4][4][4];
    #pragma unroll
    for (int i = 0; i < 4; i++)
        #pragma unroll
        for (int j = 0; j < 4; j++)
            #pragma unroll
            for (int c = 0; c < 4; c++) { acc1[i][j][c] = 0.f; acc3[i][j][c] = 0.f; }

    float4 rA[4], r1[8], r3[8];
    #pragma unroll
    for (int s = 0; s < 4; s++) rA[s] = *(const float4*)(ap[s]);
    #pragma unroll
    for (int s = 0; s < 8; s++) {
        r1[s] = *(const float4*)(W1 + (size_t)(kb + 4 * s) * IDIM);
        r3[s] = *(const float4*)(W3 + (size_t)(kb + 4 * s) * IDIM);
    }

    const int NC = HDIM / 32;   // 32
    for (int it = 0; it < NC; it++) {
        int p = it & 1;
        uint32_t aS  = sb + p * (A_H * 2);
        uint32_t b1S = sb + oB1 + p * (B_H * 2);
        uint32_t b3S = sb + oB3 + p * (B_H * 2);
        #pragma unroll
        for (int s = 0; s < 4; s++) sts_h4(aS + dA0 + s * (16 * AP * 2), rA[s]);
        #pragma unroll
        for (int s = 0; s < 8; s++) {
            sts_h4(b1S + dB0 + s * (4 * BP * 2), r1[s]);
            sts_h4(b3S + dB0 + s * (4 * BP * 2), r3[s]);
        }
        __syncthreads();
        if (it + 1 < NC) {
            int k0 = (it + 1) * 32;
            #pragma unroll
            for (int s = 0; s < 4; s++) rA[s] = *(const float4*)(ap[s] + k0);
            #pragma unroll
            for (int s = 0; s < 8; s++) {
                r1[s] = *(const float4*)(W1 + (size_t)(k0 + kb + 4 * s) * IDIM);
                r3[s] = *(const float4*)(W3 + (size_t)(k0 + kb + 4 * s) * IDIM);
            }
        }
        #pragma unroll
        for (int ks = 0; ks < 2; ks++) {
            uint32_t af[4][4];
            #pragma unroll
            for (int mt = 0; mt < 4; mt++)
                ldsm4(af[mt], aS + ((mt * 16 + rowoff) * AP + ks * 16 + khalf) * 2);
            #pragma unroll
            for (int j = 0; j < 2; j++) {
                uint32_t br[4];
                uint32_t bo = ((ks * 16 + rowoff) * BP + wn + j * 16 + khalf) * 2;
                ldsm4t(br, b1S + bo);
                #pragma unroll
                for (int mt = 0; mt < 4; mt++) {
                    mma16(acc1[mt][2 * j],     af[mt], br[0], br[1]);
                    mma16(acc1[mt][2 * j + 1], af[mt], br[2], br[3]);
                }
                ldsm4t(br, b3S + bo);
                #pragma unroll
                for (int mt = 0; mt < 4; mt++) {
                    mma16(acc3[mt][2 * j],     af[mt], br[0], br[1]);
                    mma16(acc3[mt][2 * j + 1], af[mt], br[2], br[3]);
                }
            }
        }
    }

    // epilogue: G = silu(D1) * D3 -> fp16
    #pragma unroll
    for (int mt = 0; mt < 4; mt++) {
        int r0 = mt * 16 + g;
        int r1i = r0 + 8;
        bool ok0 = (m0 + r0) < cnt, ok1 = (m0 + r1i) < cnt;
        __half* G0 = g_act + ((size_t)e * NTOK + m0 + r0) * IDIM + n0;
        __half* G1 = g_act + ((size_t)e * NTOK + m0 + r1i) * IDIM + n0;
        #pragma unroll
        for (int nt = 0; nt < 4; nt++) {
            int cc = wn + nt * 8 + 2 * t;
            if (ok0) {
                float v0 = acc1[mt][nt][0], v1 = acc1[mt][nt][1];
                float o0 = v0 / (1.0f + __expf(-v0)) * acc3[mt][nt][0];
                float o1 = v1 / (1.0f + __expf(-v1)) * acc3[mt][nt][1];
                *(__half2*)(G0 + cc) = __floats2half2_rn(o0, o1);
            }
            if (ok1) {
                float v2 = acc1[mt][nt][2], v3 = acc1[mt][nt][3];
                float o2 = v2 / (1.0f + __expf(-v2)) * acc3[mt][nt][2];
                float o3 = v3 / (1.0f + __expf(-v3)) * acc3[mt][nt][3];
                *(__half2*)(G1 + cc) = __floats2half2_rn(o2, o3);
            }
        }
    }
}

// ---------------------------------------------------------------------------
// FFN2: CTA 64(M)x128(N)xK32, 128 thr (4 warps 1Mx4N), warp 64x32.
// 3 CTAs/SM. out[tok] += wt*(G.w2) via atomicAdd (2 adds/elem, deterministic).
// ---------------------------------------------------------------------------
__global__ __launch_bounds__(128, 3)
void ffn2_mma(const float* __restrict__ w2, float* __restrict__ out) {
    extern __shared__ __half smh[];
    __shared__ float wts[64];
    __shared__ int   tk2[64];
    const int tid = threadIdx.x;
    const int e   = blockIdx.z;
    const int cnt = g_cnt[e];
    const int m0  = blockIdx.y * 64;
    if (m0 >= cnt) return;
    const int n0  = blockIdx.x * 128;

    if (tid < 64) {
        int r = m0 + tid;
        bool ok = r < cnt;
        wts[tid] = ok ? g_wt[e][r] : 0.0f;
        tk2[tid] = ok ? g_tok[e][r] : 0;
    }
    __syncthreads();
    const uint32_t sb = smem_u32(smh);
    const uint32_t oB = 2 * A_H * 2;

    // staging: A fp16 4 uint2/thread (rows ra+16s); B fp32 8 float4/thread
    const int fa = tid & 7,  ra = tid >> 3;    // ra 0..15
    const int fb = tid & 31, kb = tid >> 5;    // kb 0..3
    const __half* ga = g_act + ((size_t)e * NTOK + m0) * IDIM;
    const __half* ap[4];
    #pragma unroll
    for (int s = 0; s < 4; s++)
        ap[s] = ga + (size_t)(ra + 16 * s) * IDIM + fa * 4;
    const float* Wb = w2 + (size_t)e * IDIM * HDIM + n0 + fb * 4;
    const uint32_t dA0 = (ra * AP + fa * 4) * 2;
    const uint32_t dB0 = (kb * BP + fb * 4) * 2;

    const int wid = tid >> 5, lane = tid & 31;
    const int wn = wid * 32;
    const int g = lane >> 2, t = lane & 3;
    const int rowoff = (lane & 8) + (lane & 7);
    const int khalf  = (lane & 16) >> 1;

    float acc[4][4][4];
    #pragma unroll
    for (int i = 0; i < 4; i++)
        #pragma unroll
        for (int j = 0; j < 4; j++)
            #pragma unroll
            for (int c = 0; c < 4; c++) acc[i][j][c] = 0.f;

    uint2 rA[4];
    float4 rB[8];
    #pragma unroll
    for (int s = 0; s < 4; s++) rA[s] = *(const uint2*)(ap[s]);
    #pragma unroll
    for (int s = 0; s < 8; s++)
        rB[s] = *(const float4*)(Wb + (size_t)(kb + 4 * s) * HDIM);

    const int NC = IDIM / 32;   // 112
    for (int it = 0; it < NC; it++) {
        int p = it & 1;
        uint32_t aS = sb + p * (A_H * 2);
        uint32_t bS = sb + oB + p * (B_H * 2);
        #pragma unroll
        for (int s = 0; s < 4; s++) sts_u2(aS + dA0 + s * (16 * AP * 2), rA[s]);
        #pragma unroll
        for (int s = 0; s < 8; s++) sts_h4(bS + dB0 + s * (4 * BP * 2), rB[s]);
        __syncthreads();
        if (it + 1 < NC) {
            int k0 = (it + 1) * 32;
            #pragma unroll
            for (int s = 0; s < 4; s++) rA[s] = *(const uint2*)(ap[s] + k0);
            #pragma unroll
            for (int s = 0; s < 8; s++)
                rB[s] = *(const float4*)(Wb + (size_t)(k0 + kb + 4 * s) * HDIM);
        }
        #pragma unroll
        for (int ks = 0; ks < 2; ks++) {
            uint32_t af[4][4];
            #pragma unroll
            for (int mt = 0; mt < 4; mt++)
                ldsm4(af[mt], aS + ((mt * 16 + rowoff) * AP + ks * 16 + khalf) * 2);
            #pragma unroll
            for (int j = 0; j < 2; j++) {
                uint32_t br[4];
                ldsm4t(br, bS + ((ks * 16 + rowoff) * BP + wn + j * 16 + khalf) * 2);
                #pragma unroll
                for (int mt = 0; mt < 4; mt++) {
                    mma16(acc[mt][2 * j],     af[mt], br[0], br[1]);
                    mma16(acc[mt][2 * j + 1], af[mt], br[2], br[3]);
                }
            }
        }
    }

    // epilogue: out[tok] += wt * acc (atomic; exactly 2 adds/element overall)
    #pragma unroll
    for (int mt = 0; mt < 4; mt++) {
        int r0 = mt * 16 + g;
        int r1 = r0 + 8;
        bool ok0 = (m0 + r0) < cnt, ok1 = (m0 + r1) < cnt;
        float w0 = wts[r0], w1v = wts[r1];
        float* O0 = out + (size_t)tk2[r0] * HDIM + n0;
        float* O1 = out + (size_t)tk2[r1] * HDIM + n0;
        #pragma unroll
        for (int nt = 0; nt < 4; nt++) {
            int cc = wn + nt * 8 + 2 * t;
            if (ok0) {
                atomicAdd(&O0[cc],     w0 * acc[mt][nt][0]);
                atomicAdd(&O0[cc + 1], w0 * acc[mt][nt][1]);
            }
            if (ok1) {
                atomicAdd(&O1[cc],     w1v * acc[mt][nt][2]);
                atomicAdd(&O1[cc + 1], w1v * acc[mt][nt][3]);
            }
        }
    }
}

// ---------------------------------------------------------------------------
extern "C" void kernel_launch(void* const* d_in, const int* in_sizes, int n_in,
                              void* d_out, int out_size) {
    const float* x  = (const float*)d_in[0];
    const float* gw = (const float*)d_in[1];
    const float* w1 = (const float*)d_in[2];
    const float* w3 = (const float*)d_in[3];
    const float* w2 = (const float*)d_in[4];
    float* out = (float*)d_out;
    float* logits = out + ((size_t)out_size - (size_t)NTOK * NEXP);

    const int SMEM1 = (2 * A_H + 4 * B_H) * 2;  // 45056 B
    const int SMEM2 = (2 * A_H + 2 * B_H) * 2;  // 27648 B

    const int NZ4 = NTOK * HDIM / 4;
    zero_kernel<<<(NZ4 + 255) / 256, 256>>>((float4*)out, NZ4);
    router_kernel<<<NTOK, 256>>>(x, gw, logits);

    dim3 g1(IDIM / 128, NTOK / 64, NEXP);
    ffn1_mma<<<g1, 128, SMEM1>>>(x, w1, w3);

    dim3 g2(HDIM / 128, NTOK / 64, NEXP);
    ffn2_mma<<<g2, 128, SMEM2>>>(w2, out);
}

// round 13
// speedup vs baseline: 1.2218x; 1.2218x over previous
#include <cuda_runtime.h>
#include <cuda_fp16.h>
#include <math.h>
#include <stdint.h>

#define NTOK 4096      // B*S
#define HDIM 1024
#define IDIM 3584
#define NEXP 8

// smem pitches in fp16 halves
#define AP   40    // A tile row: 32 k + 8 pad
#define BP1  72    // ffn1 B row: 64 n + 8
#define BP2  136   // ffn2 B row: 128 n + 8
#define A_H   (128 * AP)    // 5120 halves / stage
#define B1_H  (32 * BP1)    // 2304
#define B2_H  (32 * BP2)    // 4352

// ---------------- device scratch (no allocs) ----------------
__device__ int    g_cnt[NEXP];
__device__ int    g_tok[NEXP][NTOK];
__device__ float  g_wt [NEXP][NTOK];
__device__ __half g_act[(size_t)NEXP * NTOK * IDIM];   // fp16 activations
__device__ __half g_xh [(size_t)NTOK * HDIM];          // fp16 hidden states

// ---------------- helpers ----------------
__device__ __forceinline__ uint32_t smem_u32(const void* p) {
    uint32_t a;
    asm("{ .reg .u64 t; cvta.to.shared.u64 t, %1; cvt.u32.u64 %0, t; }" : "=r"(a) : "l"(p));
    return a;
}
__device__ __forceinline__ void sts_h4(uint32_t addr, float4 v) {
    __half2 h0 = __floats2half2_rn(v.x, v.y);
    __half2 h1 = __floats2half2_rn(v.z, v.w);
    uint32_t u0 = *reinterpret_cast<uint32_t*>(&h0);
    uint32_t u1 = *reinterpret_cast<uint32_t*>(&h1);
    asm volatile("st.shared.v2.b32 [%0], {%1,%2};" :: "r"(addr), "r"(u0), "r"(u1) : "memory");
}
__device__ __forceinline__ void sts_u2(uint32_t addr, uint2 v) {
    asm volatile("st.shared.v2.b32 [%0], {%1,%2};" :: "r"(addr), "r"(v.x), "r"(v.y) : "memory");
}
__device__ __forceinline__ void ldsm4(uint32_t* r, uint32_t a) {
    asm volatile("ldmatrix.sync.aligned.m8n8.x4.shared.b16 {%0,%1,%2,%3}, [%4];"
                 : "=r"(r[0]), "=r"(r[1]), "=r"(r[2]), "=r"(r[3]) : "r"(a));
}
__device__ __forceinline__ void ldsm4t(uint32_t* r, uint32_t a) {
    asm volatile("ldmatrix.sync.aligned.m8n8.x4.trans.shared.b16 {%0,%1,%2,%3}, [%4];"
                 : "=r"(r[0]), "=r"(r[1]), "=r"(r[2]), "=r"(r[3]) : "r"(a));
}
__device__ __forceinline__ void mma16(float* d, const uint32_t* a, uint32_t b0, uint32_t b1) {
    asm volatile(
        "mma.sync.aligned.m16n8k16.row.col.f32.f16.f16.f32 "
        "{%0,%1,%2,%3},{%4,%5,%6,%7},{%8,%9},{%0,%1,%2,%3};"
        : "+f"(d[0]), "+f"(d[1]), "+f"(d[2]), "+f"(d[3])
        : "r"(a[0]), "r"(a[1]), "r"(a[2]), "r"(a[3]), "r"(b0), "r"(b1));
}

// ---------------------------------------------------------------------------
__global__ void zero_kernel() { if (threadIdx.x < NEXP) g_cnt[threadIdx.x] = 0; }

// float -> half for hidden states
__global__ void f2h_kernel(const float* __restrict__ src, int n4) {
    int i = blockIdx.x * blockDim.x + threadIdx.x;
    if (i < n4) {
        float4 v = ((const float4*)src)[i];
        __half2 h0 = __floats2half2_rn(v.x, v.y);
        __half2 h1 = __floats2half2_rn(v.z, v.w);
        uint2 u;
        u.x = *reinterpret_cast<uint32_t*>(&h0);
        u.y = *reinterpret_cast<uint32_t*>(&h1);
        ((uint2*)g_xh)[i] = u;
    }
}

// ---------------------------------------------------------------------------
// router: logits + top-2 softmax + expert lists + zero this token's out row
// ---------------------------------------------------------------------------
__global__ void router_kernel(const float* __restrict__ x,
                              const float* __restrict__ gw,
                              float* __restrict__ out,
                              float* __restrict__ logits_out) {
    int t = blockIdx.x;
    __shared__ float xs[HDIM];
    __shared__ float lg[NEXP];
    int tid = threadIdx.x;
    // zero output row for this token (256 float4 = 1024 floats)
    ((float4*)(out + (size_t)t * HDIM))[tid] = make_float4(0.f, 0.f, 0.f, 0.f);
    for (int i = tid; i < HDIM; i += 256) xs[i] = x[(size_t)t * HDIM + i];
    __syncthreads();
    int w = tid >> 5, lane = tid & 31;
    float s = 0.f;
    for (int k = lane; k < HDIM; k += 32) s += xs[k] * gw[k * NEXP + w];
    #pragma unroll
    for (int o = 16; o; o >>= 1) s += __shfl_xor_sync(0xffffffffu, s, o);
    if (lane == 0) lg[w] = s;
    __syncthreads();
    if (tid == 0) {
        #pragma unroll
        for (int e = 0; e < NEXP; e++) logits_out[(size_t)t * NEXP + e] = lg[e];
        int b0 = 0; float v0 = lg[0];
        #pragma unroll
        for (int e = 1; e < NEXP; e++) if (lg[e] > v0) { v0 = lg[e]; b0 = e; }
        int b1 = -1; float v1 = -INFINITY;
        #pragma unroll
        for (int e = 0; e < NEXP; e++) if (e != b0 && lg[e] > v1) { v1 = lg[e]; b1 = e; }
        float p1  = expf(v1 - v0);
        float inv = 1.0f / (1.0f + p1);
        int p = atomicAdd(&g_cnt[b0], 1);
        g_tok[b0][p] = t; g_wt[b0][p] = inv;
        int q = atomicAdd(&g_cnt[b1], 1);
        g_tok[b1][q] = t; g_wt[b1][q] = p1 * inv;
    }
}

// ---------------------------------------------------------------------------
// FFN1: CTA 128(M)x64(N)xK32, 128 thr (4 warps 2Mx2N), warp 64x32 dual.
// 2 CTAs/SM (independent barriers). A from g_xh fp16. G = silu(X.w1)*(X.w3).
// ---------------------------------------------------------------------------
__global__ __launch_bounds__(128, 2)
void ffn1_mma(const float* __restrict__ w1, const float* __restrict__ w3) {
    extern __shared__ __half smh[];
    __shared__ int toks[128];
    const int tid = threadIdx.x;
    const int e   = blockIdx.z;
    const int cnt = g_cnt[e];
    const int m0  = blockIdx.y * 128;
    if (m0 >= cnt) return;
    const int n0  = blockIdx.x * 64;

    {
        int r = m0 + tid;
        toks[tid] = (r < cnt) ? g_tok[e][r] : g_tok[e][0];
    }
    __syncthreads();
    const uint32_t sb = smem_u32(smh);
    const uint32_t oB1 = 2 * A_H * 2;
    const uint32_t oB3 = oB1 + 2 * B1_H * 2;

    // staging: A fp16 8 uint2/thread (rows ra+16s), B1/B3 fp32 4 float4 each
    const int fa = tid & 7,  ra = tid >> 3;    // ra 0..15
    const int fb = tid & 15, kb = tid >> 4;    // kb 0..7
    const __half* ap[8];
    uint32_t dA[8];
    #pragma unroll
    for (int s = 0; s < 8; s++) {
        ap[s] = g_xh + (size_t)toks[ra + 16 * s] * HDIM + fa * 4;
        dA[s] = ((ra + 16 * s) * AP + fa * 4) * 2;
    }
    const float* W1 = w1 + (size_t)e * HDIM * IDIM + n0 + fb * 4;
    const float* W3 = w3 + (size_t)e * HDIM * IDIM + n0 + fb * 4;
    uint32_t dB[4];
    #pragma unroll
    for (int s = 0; s < 4; s++) dB[s] = ((kb + 8 * s) * BP1 + fb * 4) * 2;

    const int wid = tid >> 5, lane = tid & 31;
    const int wm = (wid >> 1) * 64, wn = (wid & 1) * 32;
    const int g = lane >> 2, t = lane & 3;
    const int rowoff = (lane & 8) + (lane & 7);
    const int khalf  = (lane & 16) >> 1;

    float acc1[4][4][4], acc3[4][4][4];
    #pragma unroll
    for (int i = 0; i < 4; i++)
        #pragma unroll
        for (int j = 0; j < 4; j++)
            #pragma unroll
            for (int c = 0; c < 4; c++) { acc1[i][j][c] = 0.f; acc3[i][j][c] = 0.f; }

    uint2 rA[8];
    float4 r1[4], r3[4];
    #pragma unroll
    for (int s = 0; s < 8; s++) rA[s] = *(const uint2*)(ap[s]);
    #pragma unroll
    for (int s = 0; s < 4; s++) {
        r1[s] = *(const float4*)(W1 + (size_t)(kb + 8 * s) * IDIM);
        r3[s] = *(const float4*)(W3 + (size_t)(kb + 8 * s) * IDIM);
    }

    const int NC = HDIM / 32;   // 32
    for (int it = 0; it < NC; it++) {
        int p = it & 1;
        uint32_t aS  = sb + p * (A_H * 2);
        uint32_t b1S = sb + oB1 + p * (B1_H * 2);
        uint32_t b3S = sb + oB3 + p * (B1_H * 2);
        #pragma unroll
        for (int s = 0; s < 8; s++) sts_u2(aS + dA[s], rA[s]);
        #pragma unroll
        for (int s = 0; s < 4; s++) {
            sts_h4(b1S + dB[s], r1[s]);
            sts_h4(b3S + dB[s], r3[s]);
        }
        __syncthreads();
        if (it + 1 < NC) {
            int k0 = (it + 1) * 32;
            #pragma unroll
            for (int s = 0; s < 8; s++) rA[s] = *(const uint2*)(ap[s] + k0);
            #pragma unroll
            for (int s = 0; s < 4; s++) {
                r1[s] = *(const float4*)(W1 + (size_t)(k0 + kb + 8 * s) * IDIM);
                r3[s] = *(const float4*)(W3 + (size_t)(k0 + kb + 8 * s) * IDIM);
            }
        }
        #pragma unroll
        for (int ks = 0; ks < 2; ks++) {
            uint32_t af[4][4];
            #pragma unroll
            for (int mt = 0; mt < 4; mt++)
                ldsm4(af[mt], aS + ((wm + mt * 16 + rowoff) * AP + ks * 16 + khalf) * 2);
            #pragma unroll
            for (int j = 0; j < 2; j++) {
                uint32_t br[4];
                uint32_t bo = ((ks * 16 + rowoff) * BP1 + wn + j * 16 + khalf) * 2;
                ldsm4t(br, b1S + bo);
                #pragma unroll
                for (int mt = 0; mt < 4; mt++) {
                    mma16(acc1[mt][2 * j],     af[mt], br[0], br[1]);
                    mma16(acc1[mt][2 * j + 1], af[mt], br[2], br[3]);
                }
                ldsm4t(br, b3S + bo);
                #pragma unroll
                for (int mt = 0; mt < 4; mt++) {
                    mma16(acc3[mt][2 * j],     af[mt], br[0], br[1]);
                    mma16(acc3[mt][2 * j + 1], af[mt], br[2], br[3]);
                }
            }
        }
    }

    // epilogue: G = silu(D1) * D3 -> fp16
    #pragma unroll
    for (int mt = 0; mt < 4; mt++) {
        int r0 = wm + mt * 16 + g;
        int r1i = r0 + 8;
        bool ok0 = (m0 + r0) < cnt, ok1 = (m0 + r1i) < cnt;
        __half* G0 = g_act + ((size_t)e * NTOK + m0 + r0) * IDIM + n0;
        __half* G1 = g_act + ((size_t)e * NTOK + m0 + r1i) * IDIM + n0;
        #pragma unroll
        for (int nt = 0; nt < 4; nt++) {
            int cc = wn + nt * 8 + 2 * t;
            if (ok0) {
                float v0 = acc1[mt][nt][0], v1 = acc1[mt][nt][1];
                float o0 = v0 / (1.0f + __expf(-v0)) * acc3[mt][nt][0];
                float o1 = v1 / (1.0f + __expf(-v1)) * acc3[mt][nt][1];
                *(__half2*)(G0 + cc) = __floats2half2_rn(o0, o1);
            }
            if (ok1) {
                float v2 = acc1[mt][nt][2], v3 = acc1[mt][nt][3];
                float o2 = v2 / (1.0f + __expf(-v2)) * acc3[mt][nt][2];
                float o3 = v3 / (1.0f + __expf(-v3)) * acc3[mt][nt][3];
                *(__half2*)(G1 + cc) = __floats2half2_rn(o2, o3);
            }
        }
    }
}

// ---------------------------------------------------------------------------
// FFN2: CTA 128(M)x128(N)xK32, 128 thr (4 warps 2Mx2N), warp 64x64.
// 2 CTAs/SM. out[tok] += wt*(G.w2) via atomicAdd (2 adds/elem, deterministic).
// ---------------------------------------------------------------------------
__global__ __launch_bounds__(128, 2)
void ffn2_mma(const float* __restrict__ w2, float* __restrict__ out) {
    extern __shared__ __half smh[];
    __shared__ float wts[128];
    __shared__ int   tk2[128];
    const int tid = threadIdx.x;
    const int e   = blockIdx.z;
    const int cnt = g_cnt[e];
    const int m0  = blockIdx.y * 128;
    if (m0 >= cnt) return;
    const int n0  = blockIdx.x * 128;

    {
        int r = m0 + tid;
        bool ok = r < cnt;
        wts[tid] = ok ? g_wt[e][r] : 0.0f;
        tk2[tid] = ok ? g_tok[e][r] : 0;
    }
    __syncthreads();
    const uint32_t sb = smem_u32(smh);
    const uint32_t oB = 2 * A_H * 2;

    // staging: A fp16 8 uint2/thread (rows ra+16s); B fp32 8 float4/thread
    const int fa = tid & 7,  ra = tid >> 3;    // ra 0..15
    const int fb = tid & 31, kb = tid >> 5;    // kb 0..3
    const __half* ga = g_act + ((size_t)e * NTOK + m0) * IDIM;
    const __half* ap[8];
    uint32_t dA[8];
    #pragma unroll
    for (int s = 0; s < 8; s++) {
        ap[s] = ga + (size_t)(ra + 16 * s) * IDIM + fa * 4;
        dA[s] = ((ra + 16 * s) * AP + fa * 4) * 2;
    }
    const float* Wb = w2 + (size_t)e * IDIM * HDIM + n0 + fb * 4;
    uint32_t dB[8];
    #pragma unroll
    for (int s = 0; s < 8; s++) dB[s] = ((kb + 4 * s) * BP2 + fb * 4) * 2;

    const int wid = tid >> 5, lane = tid & 31;
    const int wm = (wid >> 1) * 64, wn = (wid & 1) * 64;
    const int g = lane >> 2, t = lane & 3;
    const int rowoff = (lane & 8) + (lane & 7);
    const int khalf  = (lane & 16) >> 1;

    float acc[4][8][4];
    #pragma unroll
    for (int i = 0; i < 4; i++)
        #pragma unroll
        for (int j = 0; j < 8; j++)
            #pragma unroll
            for (int c = 0; c < 4; c++) acc[i][j][c] = 0.f;

    uint2 rA[8];
    float4 rB[8];
    #pragma unroll
    for (int s = 0; s < 8; s++) rA[s] = *(const uint2*)(ap[s]);
    #pragma unroll
    for (int s = 0; s < 8; s++)
        rB[s] = *(const float4*)(Wb + (size_t)(kb + 4 * s) * HDIM);

    const int NC = IDIM / 32;   // 112
    for (int it = 0; it < NC; it++) {
        int p = it & 1;
        uint32_t aS = sb + p * (A_H * 2);
        uint32_t bS = sb + oB + p * (B2_H * 2);
        #pragma unroll
        for (int s = 0; s < 8; s++) sts_u2(aS + dA[s], rA[s]);
        #pragma unroll
        for (int s = 0; s < 8; s++) sts_h4(bS + dB[s], rB[s]);
        __syncthreads();
        if (it + 1 < NC) {
            int k0 = (it + 1) * 32;
            #pragma unroll
            for (int s = 0; s < 8; s++) rA[s] = *(const uint2*)(ap[s] + k0);
            #pragma unroll
            for (int s = 0; s < 8; s++)
                rB[s] = *(const float4*)(Wb + (size_t)(k0 + kb + 4 * s) * HDIM);
        }
        #pragma unroll
        for (int ks = 0; ks < 2; ks++) {
            uint32_t af[4][4];
            #pragma unroll
            for (int mt = 0; mt < 4; mt++)
                ldsm4(af[mt], aS + ((wm + mt * 16 + rowoff) * AP + ks * 16 + khalf) * 2);
            #pragma unroll
            for (int j = 0; j < 4; j++) {
                uint32_t br[4];
                ldsm4t(br, bS + ((ks * 16 + rowoff) * BP2 + wn + j * 16 + khalf) * 2);
                #pragma unroll
                for (int mt = 0; mt < 4; mt++) {
                    mma16(acc[mt][2 * j],     af[mt], br[0], br[1]);
                    mma16(acc[mt][2 * j + 1], af[mt], br[2], br[3]);
                }
            }
        }
    }

    // epilogue: out[tok] += wt * acc (atomic; exactly 2 adds/element overall)
    #pragma unroll
    for (int mt = 0; mt < 4; mt++) {
        int r0 = wm + mt * 16 + g;
        int r1 = r0 + 8;
        bool ok0 = (m0 + r0) < cnt, ok1 = (m0 + r1) < cnt;
        float w0 = wts[r0], w1v = wts[r1];
        float* O0 = out + (size_t)tk2[r0] * HDIM + n0;
        float* O1 = out + (size_t)tk2[r1] * HDIM + n0;
        #pragma unroll
        for (int nt = 0; nt < 8; nt++) {
            int cc = wn + nt * 8 + 2 * t;
            if (ok0) {
                atomicAdd(&O0[cc],     w0 * acc[mt][nt][0]);
                atomicAdd(&O0[cc + 1], w0 * acc[mt][nt][1]);
            }
            if (ok1) {
                atomicAdd(&O1[cc],     w1v * acc[mt][nt][2]);
                atomicAdd(&O1[cc + 1], w1v * acc[mt][nt][3]);
            }
        }
    }
}

// ---------------------------------------------------------------------------
extern "C" void kernel_launch(void* const* d_in, const int* in_sizes, int n_in,
                              void* d_out, int out_size) {
    const float* x  = (const float*)d_in[0];
    const float* gw = (const float*)d_in[1];
    const float* w1 = (const float*)d_in[2];
    const float* w3 = (const float*)d_in[3];
    const float* w2 = (const float*)d_in[4];
    float* out = (float*)d_out;
    float* logits = out + ((size_t)out_size - (size_t)NTOK * NEXP);

    const int SMEM1 = (2 * A_H + 4 * B1_H) * 2;  // 38912 B
    const int SMEM2 = (2 * A_H + 2 * B2_H) * 2;  // 37888 B

    zero_kernel<<<1, 32>>>();
    const int NX4 = NTOK * HDIM / 4;
    f2h_kernel<<<(NX4 + 255) / 256, 256>>>(x, NX4);
    router_kernel<<<NTOK, 256>>>(x, gw, out, logits);

    dim3 g1(IDIM / 64, NTOK / 128, NEXP);
    ffn1_mma<<<g1, 128, SMEM1>>>(w1, w3);

    dim3 g2(HDIM / 128, NTOK / 128, NEXP);
    ffn2_mma<<<g2, 128, SMEM2>>>(w2, out);
}